// round 12
// baseline (speedup 1.0000x reference)
#include <cuda_runtime.h>
#include <cuda_fp16.h>
#include <cstdint>

#define D_MODEL 1024
#define SEQ     2048
#define BATCH   2
#define NHEAD   16
#define DK      64
#define MTOT    (BATCH * SEQ)

// Scratch (allocation-free rule)
__device__ float g_Q[BATCH * SEQ * D_MODEL];
__device__ float g_K[BATCH * SEQ * D_MODEL];
__device__ float g_V[BATCH * SEQ * D_MODEL];
__device__ float g_att[BATCH * SEQ * D_MODEL];
__device__ uint32_t g_Wth[4 * D_MODEL * D_MODEL / 2];  // W^T as fp16 pairs

// ---------------------------------------------------------------------------
__device__ __forceinline__ uint32_t f2h2(float lo, float hi) {
    uint32_t r;
    asm("cvt.rn.f16x2.f32 %0, %2, %1;" : "=r"(r) : "f"(lo), "f"(hi));
    return r;
}

__device__ __forceinline__ void mma_f16(float* d, const uint32_t* a,
                                        const uint32_t* b, const float* c) {
    asm volatile(
        "mma.sync.aligned.m16n8k16.row.col.f32.f16.f16.f32 "
        "{%0,%1,%2,%3}, {%4,%5,%6,%7}, {%8,%9}, {%10,%11,%12,%13};\n"
        : "=f"(d[0]), "=f"(d[1]), "=f"(d[2]), "=f"(d[3])
        : "r"(a[0]), "r"(a[1]), "r"(a[2]), "r"(a[3]),
          "r"(b[0]), "r"(b[1]),
          "f"(c[0]), "f"(c[1]), "f"(c[2]), "f"(c[3]));
}

// ---------------------------------------------------------------------------
// Transpose + cvt: g_Wth[z][n][k] = fp16(W_z[k][n]), packed 2 halfs/u32.
// (R10-proven, unchanged)
// ---------------------------------------------------------------------------
__global__ __launch_bounds__(256)
void transpose_h2_kernel(const float* __restrict__ Wq, const float* __restrict__ Wk,
                         const float* __restrict__ Wv, const float* __restrict__ Wo,
                         uint32_t* __restrict__ Wth) {
    __shared__ float tile[32][33];
    const float* W = (blockIdx.z == 0) ? Wq : (blockIdx.z == 1) ? Wk
                   : (blockIdx.z == 2) ? Wv : Wo;
    uint32_t* T = Wth + (size_t)blockIdx.z * D_MODEL * (D_MODEL / 2);
    int tx = threadIdx.x, ty = threadIdx.y;   // 32 x 8
    int x = blockIdx.x * 32 + tx;
#pragma unroll
    for (int i = 0; i < 4; i++)
        tile[ty + i * 8][tx] = W[(size_t)(blockIdx.y * 32 + ty + i * 8) * D_MODEL + x];
    __syncthreads();
    int lid = ty * 32 + tx;
#pragma unroll
    for (int j = 0; j < 2; j++) {
        int o = j * 256 + lid;
        int n_loc = o >> 4;
        int kp = o & 15;
        float lo = tile[kp * 2][n_loc];
        float hi = tile[kp * 2 + 1][n_loc];
        int n = blockIdx.x * 32 + n_loc;
        T[(size_t)n * (D_MODEL / 2) + blockIdx.y * 16 + kp] = f2h2(lo, hi);
    }
}

// ---------------------------------------------------------------------------
// FP16 GEMM (R10-proven, unchanged): C = A(f32) @ Wth(fp16 NxK)^T, 128x128.
// ---------------------------------------------------------------------------
#define GKC 32
#define GSTAGES (D_MODEL / GKC)   // 32

__device__ __forceinline__ void gemm_f16_body(const float* __restrict__ A,
                                              const uint32_t* __restrict__ Bt,
                                              float* __restrict__ C,
                                              int bm, int bn, int N) {
    __shared__ uint32_t As32[2][128][20];
    __shared__ uint32_t Bs32[2][128][20];

    const int tid = threadIdx.x;
    const int w = tid >> 5, lane = tid & 31;
    const int wr = w >> 1, wc = w & 1;
    const int gid = lane >> 2, tig = lane & 3;

    float acc[2][8][4] = {};

    const int arow = tid >> 1, akh = (tid & 1) * 16;
    float4 av[4];
    uint4 bv[2];

    auto ldg_stage = [&](int k0) {
#pragma unroll
        for (int i = 0; i < 4; i++)
            av[i] = *(const float4*)(A + (size_t)(bm + arow) * D_MODEL + k0 + akh + i * 4);
#pragma unroll
        for (int j = 0; j < 2; j++) {
            int id = j * 256 + tid;
            int n = id >> 2, kq = id & 3;
            bv[j] = *(const uint4*)(Bt + (size_t)(bn + n) * (D_MODEL / 2) + k0 / 2 + kq * 4);
        }
    };
    auto sts_stage = [&](int b) {
        const float* f = (const float*)av;
        uint32_t h[8];
#pragma unroll
        for (int j = 0; j < 8; j++) h[j] = f2h2(f[2 * j], f[2 * j + 1]);
        *(uint4*)&As32[b][arow][(tid & 1) * 8] = *(uint4*)&h[0];
        *(uint4*)&As32[b][arow][(tid & 1) * 8 + 4] = *(uint4*)&h[4];
#pragma unroll
        for (int j = 0; j < 2; j++) {
            int id = j * 256 + tid;
            int n = id >> 2, kq = id & 3;
            *(uint4*)&Bs32[b][n][kq * 4] = bv[j];
        }
    };

    ldg_stage(0);
    sts_stage(0);
    __syncthreads();

    int buf = 0;
    for (int ks = 0; ks < GSTAGES; ks++, buf ^= 1) {
        const bool more = (ks + 1) < GSTAGES;
        if (more) ldg_stage((ks + 1) * GKC);

#pragma unroll
        for (int kk = 0; kk < 2; kk++) {
            uint32_t af[2][4];
#pragma unroll
            for (int mt = 0; mt < 2; mt++) {
                int rb = wr * 32 + mt * 16 + gid;
                af[mt][0] = As32[buf][rb][kk * 8 + tig];
                af[mt][1] = As32[buf][rb + 8][kk * 8 + tig];
                af[mt][2] = As32[buf][rb][kk * 8 + tig + 4];
                af[mt][3] = As32[buf][rb + 8][kk * 8 + tig + 4];
            }
            uint32_t bf[8][2];
#pragma unroll
            for (int nt = 0; nt < 8; nt++) {
                int col = wc * 64 + nt * 8 + gid;
                bf[nt][0] = Bs32[buf][col][kk * 8 + tig];
                bf[nt][1] = Bs32[buf][col][kk * 8 + tig + 4];
            }
#pragma unroll
            for (int mt = 0; mt < 2; mt++)
#pragma unroll
                for (int nt = 0; nt < 8; nt++)
                    mma_f16(acc[mt][nt], af[mt], bf[nt], acc[mt][nt]);
        }

        if (more) {
            sts_stage(buf ^ 1);
            __syncthreads();
        }
    }

#pragma unroll
    for (int mt = 0; mt < 2; mt++)
#pragma unroll
        for (int nt = 0; nt < 8; nt++) {
            int row = bm + wr * 32 + mt * 16 + gid;
            int col = bn + wc * 64 + nt * 8 + 2 * tig;
            *(float2*)(C + (size_t)row * N + col) =
                make_float2(acc[mt][nt][0], acc[mt][nt][1]);
            *(float2*)(C + (size_t)(row + 8) * N + col) =
                make_float2(acc[mt][nt][2], acc[mt][nt][3]);
        }
}

__global__ __launch_bounds__(256)
void gemm_qkv_f16(const float* __restrict__ x, const uint32_t* __restrict__ Wth) {
    float* C = (blockIdx.z == 0) ? g_Q : (blockIdx.z == 1) ? g_K : g_V;
    gemm_f16_body(x, Wth + (size_t)blockIdx.z * D_MODEL * (D_MODEL / 2), C,
                  blockIdx.y * 128, blockIdx.x * 128, D_MODEL);
}

__global__ __launch_bounds__(256)
void gemm_o_f16(const float* __restrict__ Aat, const uint32_t* __restrict__ Wth,
                float* __restrict__ C) {
    gemm_f16_body(Aat, Wth + (size_t)3 * D_MODEL * (D_MODEL / 2), C,
                  blockIdx.y * 128, blockIdx.x * 128, D_MODEL);
}

// ---------------------------------------------------------------------------
// Flash attention, FP16 m16n8k16, ldmatrix-free.
// CTA = (128 q, head, batch), 256 threads; warp w owns q rows [w*16, w*16+16).
// smem: Qh[128][36] (staging only), Kh[64][36] (kv rows x d-pairs),
//       Vp[32][72]  (kv-PAIR rows x d cols; pairing done at gmem load).
// P stays entirely in registers (C-fragment kv-pairs == A-fragment pairs).
// ---------------------------------------------------------------------------
#define KS  36   // Qh/Kh row stride (u32)
#define VSP 72   // Vp row stride (u32)

__global__ __launch_bounds__(256)
void attn_kernel(const float* __restrict__ Q, const float* __restrict__ K,
                 const float* __restrict__ V, float* __restrict__ O) {
    __shared__ uint32_t Qh[128 * KS];
    __shared__ uint32_t Kh[64 * KS];
    __shared__ uint32_t Vp[32 * VSP];

    const int qt = blockIdx.x, h = blockIdx.y, b = blockIdx.z;
    const int tid = threadIdx.x;
    const int w = tid >> 5, lane = tid & 31;
    const int gid = lane >> 2, tig = lane & 3;

    const float* Qbase = Q + ((size_t)b * SEQ + qt * 128) * D_MODEL + h * DK;
    const float* Kbase = K + (size_t)b * SEQ * D_MODEL + h * DK;
    const float* Vbase = V + (size_t)b * SEQ * D_MODEL + h * DK;

    // Load + convert Q tile (128 x 64 f32 -> fp16 pairs along d)
#pragma unroll
    for (int i = 0; i < 8; i++) {
        int idx = i * 256 + tid;
        int r = idx >> 4, c = (idx & 15) * 4;
        float4 v = *(const float4*)(Qbase + (size_t)r * D_MODEL + c);
        *(uint2*)&Qh[r * KS + c / 2] = make_uint2(f2h2(v.x, v.y), f2h2(v.z, v.w));
    }
    __syncthreads();

    // Hoist Q fragments (warp's 16 rows, 4 k16-chunks).
    const int r0 = w * 16 + gid;
    uint32_t qf[4][4];
#pragma unroll
    for (int kc = 0; kc < 4; kc++) {
        qf[kc][0] = Qh[r0 * KS + kc * 8 + tig];
        qf[kc][1] = Qh[(r0 + 8) * KS + kc * 8 + tig];
        qf[kc][2] = Qh[r0 * KS + kc * 8 + tig + 4];
        qf[kc][3] = Qh[(r0 + 8) * KS + kc * 8 + tig + 4];
    }

    float o[8][4] = {};
    float m0 = -1e30f, m1 = -1e30f, l0 = 0.f, l1 = 0.f;

    for (int kt = 0; kt < SEQ / 64; kt++) {
        __syncthreads();   // all warps done reading Kh/Vp of previous iter
        const float* kb = Kbase + (size_t)kt * 64 * D_MODEL;
        const float* vb = Vbase + (size_t)kt * 64 * D_MODEL;
        // K tile: 64 rows x 64 d -> Kh[kv][d-pairs]
#pragma unroll
        for (int i = 0; i < 4; i++) {
            int idx = i * 256 + tid;
            int r = idx >> 4, c = (idx & 15) * 4;
            float4 k4 = *(const float4*)(kb + (size_t)r * D_MODEL + c);
            *(uint2*)&Kh[r * KS + c / 2] = make_uint2(f2h2(k4.x, k4.y), f2h2(k4.z, k4.w));
        }
        // V tile: pair kv rows at load time -> Vp[kvpair][d], coalesced STS.128
#pragma unroll
        for (int j = 0; j < 2; j++) {
            int idx = j * 256 + tid;
            int rp = idx >> 4, c = (idx & 15) * 4;
            float4 va = *(const float4*)(vb + (size_t)(2 * rp) * D_MODEL + c);
            float4 vb4 = *(const float4*)(vb + (size_t)(2 * rp + 1) * D_MODEL + c);
            uint4 pk = make_uint4(f2h2(va.x, vb4.x), f2h2(va.y, vb4.y),
                                  f2h2(va.z, vb4.z), f2h2(va.w, vb4.w));
            *(uint4*)&Vp[rp * VSP + c] = pk;
        }
        __syncthreads();

        // S = Q @ K^T  (16 x 64 per warp; 4 k16-chunks x 8 n-tiles)
        float s[8][4] = {};
#pragma unroll
        for (int kc = 0; kc < 4; kc++) {
#pragma unroll
            for (int nt = 0; nt < 8; nt++) {
                uint32_t kf[2];
                int kvp = nt * 8 + gid;
                kf[0] = Kh[kvp * KS + kc * 8 + tig];
                kf[1] = Kh[kvp * KS + kc * 8 + tig + 4];
                mma_f16(s[nt], qf[kc], kf, s[nt]);
            }
        }

        const float scale = 0.125f;   // 1/sqrt(64)
        float mx0 = -1e30f, mx1 = -1e30f;
#pragma unroll
        for (int nt = 0; nt < 8; nt++) {
#pragma unroll
            for (int i = 0; i < 4; i++) s[nt][i] *= scale;
            mx0 = fmaxf(mx0, fmaxf(s[nt][0], s[nt][1]));
            mx1 = fmaxf(mx1, fmaxf(s[nt][2], s[nt][3]));
        }
        mx0 = fmaxf(mx0, __shfl_xor_sync(0xffffffffu, mx0, 1));
        mx0 = fmaxf(mx0, __shfl_xor_sync(0xffffffffu, mx0, 2));
        mx1 = fmaxf(mx1, __shfl_xor_sync(0xffffffffu, mx1, 1));
        mx1 = fmaxf(mx1, __shfl_xor_sync(0xffffffffu, mx1, 2));

        float nm0 = fmaxf(m0, mx0), nm1 = fmaxf(m1, mx1);
        float corr0 = __expf(m0 - nm0), corr1 = __expf(m1 - nm1);
        m0 = nm0; m1 = nm1;

        float rs0 = 0.f, rs1 = 0.f;
#pragma unroll
        for (int nt = 0; nt < 8; nt++) {
            s[nt][0] = __expf(s[nt][0] - nm0);
            s[nt][1] = __expf(s[nt][1] - nm0);
            s[nt][2] = __expf(s[nt][2] - nm1);
            s[nt][3] = __expf(s[nt][3] - nm1);
            rs0 += s[nt][0] + s[nt][1];
            rs1 += s[nt][2] + s[nt][3];
        }
        rs0 += __shfl_xor_sync(0xffffffffu, rs0, 1);
        rs0 += __shfl_xor_sync(0xffffffffu, rs0, 2);
        rs1 += __shfl_xor_sync(0xffffffffu, rs1, 1);
        rs1 += __shfl_xor_sync(0xffffffffu, rs1, 2);
        l0 = l0 * corr0 + rs0;
        l1 = l1 * corr1 + rs1;

#pragma unroll
        for (int nt = 0; nt < 8; nt++) {
            o[nt][0] *= corr0; o[nt][1] *= corr0;
            o[nt][2] *= corr1; o[nt][3] *= corr1;
        }

        // O += P @ V: P A-fragments straight from registers (kv pairs are
        // already adjacent in the C fragment); V B-fragments from Vp.
#pragma unroll
        for (int kc = 0; kc < 4; kc++) {
            uint32_t pa[4];
            pa[0] = f2h2(s[2 * kc][0], s[2 * kc][1]);
            pa[1] = f2h2(s[2 * kc][2], s[2 * kc][3]);
            pa[2] = f2h2(s[2 * kc + 1][0], s[2 * kc + 1][1]);
            pa[3] = f2h2(s[2 * kc + 1][2], s[2 * kc + 1][3]);
#pragma unroll
            for (int nt = 0; nt < 8; nt++) {
                uint32_t vf[2];
                int col = nt * 8 + gid;
                vf[0] = Vp[(kc * 8 + tig) * VSP + col];
                vf[1] = Vp[(kc * 8 + tig + 4) * VSP + col];
                mma_f16(o[nt], pa, vf, o[nt]);
            }
        }
    }

    // Normalize and write concat layout (B, S, D)
    float inv0 = 1.0f / l0, inv1 = 1.0f / l1;
    float* obase = O + ((size_t)b * SEQ + qt * 128) * D_MODEL + h * DK;
#pragma unroll
    for (int nt = 0; nt < 8; nt++) {
        int col = nt * 8 + 2 * tig;
        *(float2*)(obase + (size_t)r0 * D_MODEL + col) =
            make_float2(o[nt][0] * inv0, o[nt][1] * inv0);
        *(float2*)(obase + (size_t)(r0 + 8) * D_MODEL + col) =
            make_float2(o[nt][2] * inv1, o[nt][3] * inv1);
    }
}

// ---------------------------------------------------------------------------
extern "C" void kernel_launch(void* const* d_in, const int* in_sizes, int n_in,
                              void* d_out, int out_size) {
    const float* x  = (const float*)d_in[0];
    const float* Wq = (const float*)d_in[1];
    const float* Wk = (const float*)d_in[2];
    const float* Wv = (const float*)d_in[3];
    const float* Wo = (const float*)d_in[4];
    float* out = (float*)d_out;

    float *Qp, *Kp, *Vp_, *Ap;
    uint32_t* Wth;
    cudaGetSymbolAddress((void**)&Qp, g_Q);
    cudaGetSymbolAddress((void**)&Kp, g_K);
    cudaGetSymbolAddress((void**)&Vp_, g_V);
    cudaGetSymbolAddress((void**)&Ap, g_att);
    cudaGetSymbolAddress((void**)&Wth, g_Wth);

    // W^T -> fp16
    transpose_h2_kernel<<<dim3(32, 32, 4), dim3(32, 8)>>>(Wq, Wk, Wv, Wo, Wth);

    // QKV projections (fp16 tensor path)
    gemm_qkv_f16<<<dim3(8, 32, 3), 256>>>(x, Wth);

    // Attention (fp16 tensor path, register-resident P)
    attn_kernel<<<dim3(SEQ / 128, NHEAD, BATCH), 256>>>(Qp, Kp, Vp_, Ap);

    // Output projection (fp16 tensor path)
    gemm_o_f16<<<dim3(8, 32, 1), 256>>>(Ap, Wth, out);
}

// round 15
// speedup vs baseline: 1.6519x; 1.6519x over previous
#include <cuda_runtime.h>
#include <cuda_fp16.h>
#include <cstdint>

#define D_MODEL 1024
#define SEQ     2048
#define BATCH   2
#define NHEAD   16
#define DK      64
#define MTOT    (BATCH * SEQ)
#define DH2     (D_MODEL / 2)     // u32 (half-pair) row stride

// Scratch (allocation-free rule) — all inter-kernel tensors fp16-packed
__device__ uint32_t g_Qh[MTOT * DH2];
__device__ uint32_t g_Kh[MTOT * DH2];
__device__ uint32_t g_Vh[MTOT * DH2];
__device__ uint32_t g_Ah[MTOT * DH2];                  // attention output
__device__ uint32_t g_Wth[4 * D_MODEL * DH2];          // W^T as fp16 pairs

// ---------------------------------------------------------------------------
__device__ __forceinline__ uint32_t f2h2(float lo, float hi) {
    uint32_t r;
    asm("cvt.rn.f16x2.f32 %0, %2, %1;" : "=r"(r) : "f"(lo), "f"(hi));
    return r;
}
__device__ __forceinline__ uint32_t prmt(uint32_t a, uint32_t b, uint32_t sel) {
    uint32_t r;
    asm("prmt.b32 %0, %1, %2, %3;" : "=r"(r) : "r"(a), "r"(b), "r"(sel));
    return r;
}

__device__ __forceinline__ void mma_f16(float* d, const uint32_t* a,
                                        const uint32_t* b, const float* c) {
    asm volatile(
        "mma.sync.aligned.m16n8k16.row.col.f32.f16.f16.f32 "
        "{%0,%1,%2,%3}, {%4,%5,%6,%7}, {%8,%9}, {%10,%11,%12,%13};\n"
        : "=f"(d[0]), "=f"(d[1]), "=f"(d[2]), "=f"(d[3])
        : "r"(a[0]), "r"(a[1]), "r"(a[2]), "r"(a[3]),
          "r"(b[0]), "r"(b[1]),
          "f"(c[0]), "f"(c[1]), "f"(c[2]), "f"(c[3]));
}

// ---------------------------------------------------------------------------
// Transpose + cvt: g_Wth[z][n][k] = fp16(W_z[k][n])  (R10-proven, unchanged)
// ---------------------------------------------------------------------------
__global__ __launch_bounds__(256)
void transpose_h2_kernel(const float* __restrict__ Wq, const float* __restrict__ Wk,
                         const float* __restrict__ Wv, const float* __restrict__ Wo,
                         uint32_t* __restrict__ Wth) {
    __shared__ float tile[32][33];
    const float* W = (blockIdx.z == 0) ? Wq : (blockIdx.z == 1) ? Wk
                   : (blockIdx.z == 2) ? Wv : Wo;
    uint32_t* T = Wth + (size_t)blockIdx.z * D_MODEL * DH2;
    int tx = threadIdx.x, ty = threadIdx.y;   // 32 x 8
    int x = blockIdx.x * 32 + tx;
#pragma unroll
    for (int i = 0; i < 4; i++)
        tile[ty + i * 8][tx] = W[(size_t)(blockIdx.y * 32 + ty + i * 8) * D_MODEL + x];
    __syncthreads();
    int lid = ty * 32 + tx;
#pragma unroll
    for (int j = 0; j < 2; j++) {
        int o = j * 256 + lid;
        int n_loc = o >> 4;
        int kp = o & 15;
        float lo = tile[kp * 2][n_loc];
        float hi = tile[kp * 2 + 1][n_loc];
        int n = blockIdx.x * 32 + n_loc;
        T[(size_t)n * DH2 + blockIdx.y * 16 + kp] = f2h2(lo, hi);
    }
}

// ---------------------------------------------------------------------------
// FP16 GEMM (R10-proven core). A: f32 or fp16-packed; C: f32 or fp16-packed.
// 128x128 tile, KC=32, double-buffered ldg->reg->sts.
// ---------------------------------------------------------------------------
#define GKC 32
#define GSTAGES (D_MODEL / GKC)   // 32

template<bool A_HALF, bool C_HALF>
__device__ __forceinline__ void gemm_f16_body(const void* __restrict__ Avoid,
                                              const uint32_t* __restrict__ Bt,
                                              void* __restrict__ Cvoid,
                                              int bm, int bn, int N) {
    __shared__ uint32_t As32[2][128][20];
    __shared__ uint32_t Bs32[2][128][20];

    const float* Af = (const float*)Avoid;
    const uint32_t* Ah = (const uint32_t*)Avoid;

    const int tid = threadIdx.x;
    const int w = tid >> 5, lane = tid & 31;
    const int wr = w >> 1, wc = w & 1;
    const int gid = lane >> 2, tig = lane & 3;

    float acc[2][8][4] = {};

    const int arow = tid >> 1, ak = (tid & 1);
    float4 av[4];
    uint4 avh[2];
    uint4 bv[2];

    auto ldg_stage = [&](int k0) {
        if (A_HALF) {
#pragma unroll
            for (int i = 0; i < 2; i++)
                avh[i] = *(const uint4*)(Ah + (size_t)(bm + arow) * DH2 + k0 / 2
                                             + ak * 8 + i * 4);
        } else {
#pragma unroll
            for (int i = 0; i < 4; i++)
                av[i] = *(const float4*)(Af + (size_t)(bm + arow) * D_MODEL + k0
                                             + ak * 16 + i * 4);
        }
#pragma unroll
        for (int j = 0; j < 2; j++) {
            int id = j * 256 + tid;
            int n = id >> 2, kq = id & 3;
            bv[j] = *(const uint4*)(Bt + (size_t)(bn + n) * DH2 + k0 / 2 + kq * 4);
        }
    };
    auto sts_stage = [&](int b) {
        if (A_HALF) {
            *(uint4*)&As32[b][arow][ak * 8] = avh[0];
            *(uint4*)&As32[b][arow][ak * 8 + 4] = avh[1];
        } else {
            const float* f = (const float*)av;
            uint32_t hh[8];
#pragma unroll
            for (int j = 0; j < 8; j++) hh[j] = f2h2(f[2 * j], f[2 * j + 1]);
            *(uint4*)&As32[b][arow][ak * 8] = *(uint4*)&hh[0];
            *(uint4*)&As32[b][arow][ak * 8 + 4] = *(uint4*)&hh[4];
        }
#pragma unroll
        for (int j = 0; j < 2; j++) {
            int id = j * 256 + tid;
            int n = id >> 2, kq = id & 3;
            *(uint4*)&Bs32[b][n][kq * 4] = bv[j];
        }
    };

    ldg_stage(0);
    sts_stage(0);
    __syncthreads();

    int buf = 0;
    for (int ks = 0; ks < GSTAGES; ks++, buf ^= 1) {
        const bool more = (ks + 1) < GSTAGES;
        if (more) ldg_stage((ks + 1) * GKC);

#pragma unroll
        for (int kk = 0; kk < 2; kk++) {
            uint32_t af[2][4];
#pragma unroll
            for (int mt = 0; mt < 2; mt++) {
                int rb = wr * 32 + mt * 16 + gid;
                af[mt][0] = As32[buf][rb][kk * 8 + tig];
                af[mt][1] = As32[buf][rb + 8][kk * 8 + tig];
                af[mt][2] = As32[buf][rb][kk * 8 + tig + 4];
                af[mt][3] = As32[buf][rb + 8][kk * 8 + tig + 4];
            }
            uint32_t bf[8][2];
#pragma unroll
            for (int nt = 0; nt < 8; nt++) {
                int col = wc * 64 + nt * 8 + gid;
                bf[nt][0] = Bs32[buf][col][kk * 8 + tig];
                bf[nt][1] = Bs32[buf][col][kk * 8 + tig + 4];
            }
#pragma unroll
            for (int mt = 0; mt < 2; mt++)
#pragma unroll
                for (int nt = 0; nt < 8; nt++)
                    mma_f16(acc[mt][nt], af[mt], bf[nt], acc[mt][nt]);
        }

        if (more) {
            sts_stage(buf ^ 1);
            __syncthreads();
        }
    }

#pragma unroll
    for (int mt = 0; mt < 2; mt++)
#pragma unroll
        for (int nt = 0; nt < 8; nt++) {
            int row = bm + wr * 32 + mt * 16 + gid;
            if (C_HALF) {
                uint32_t* Ch = (uint32_t*)Cvoid;
                int ucol = (bn + wc * 64 + nt * 8) / 2 + tig;
                Ch[(size_t)row * (N / 2) + ucol] = f2h2(acc[mt][nt][0], acc[mt][nt][1]);
                Ch[(size_t)(row + 8) * (N / 2) + ucol] = f2h2(acc[mt][nt][2], acc[mt][nt][3]);
            } else {
                float* Cf = (float*)Cvoid;
                int col = bn + wc * 64 + nt * 8 + 2 * tig;
                *(float2*)(Cf + (size_t)row * N + col) =
                    make_float2(acc[mt][nt][0], acc[mt][nt][1]);
                *(float2*)(Cf + (size_t)(row + 8) * N + col) =
                    make_float2(acc[mt][nt][2], acc[mt][nt][3]);
            }
        }
}

__global__ __launch_bounds__(256)
void gemm_qkv_f16(const float* __restrict__ x, const uint32_t* __restrict__ Wth,
                  uint32_t* __restrict__ Qh, uint32_t* __restrict__ Kh,
                  uint32_t* __restrict__ Vh) {
    uint32_t* C = (blockIdx.z == 0) ? Qh : (blockIdx.z == 1) ? Kh : Vh;
    gemm_f16_body<false, true>(x, Wth + (size_t)blockIdx.z * D_MODEL * DH2, C,
                               blockIdx.y * 128, blockIdx.x * 128, D_MODEL);
}

__global__ __launch_bounds__(256)
void gemm_o_f16(const uint32_t* __restrict__ Ah, const uint32_t* __restrict__ Wth,
                float* __restrict__ C) {
    gemm_f16_body<true, false>(Ah, Wth + (size_t)3 * D_MODEL * DH2, C,
                               blockIdx.y * 128, blockIdx.x * 128, D_MODEL);
}

// ---------------------------------------------------------------------------
// Flash attention, FP16 m16n8k16, fully fp16 I/O, register-resident P.
// CTA = (128 q, head, batch), 256 threads; warp w owns q rows [w*16, w*16+16).
// smem: Qh[128][36], Kh[64][36] (kv x d-pairs), Vp[32][72] (kv-pairs x d).
// ---------------------------------------------------------------------------
#define KS  36
#define VSP 72

__global__ __launch_bounds__(256)
void attn_kernel(const uint32_t* __restrict__ Qg, const uint32_t* __restrict__ Kg,
                 const uint32_t* __restrict__ Vg, uint32_t* __restrict__ Og) {
    __shared__ uint32_t Qh[128 * KS];
    __shared__ uint32_t Kh[64 * KS];
    __shared__ uint32_t Vp[32 * VSP];

    const int qt = blockIdx.x, h = blockIdx.y, b = blockIdx.z;
    const int tid = threadIdx.x;
    const int w = tid >> 5, lane = tid & 31;
    const int gid = lane >> 2, tig = lane & 3;

    const uint32_t* Qb = Qg + ((size_t)b * SEQ + qt * 128) * DH2 + h * (DK / 2);
    const uint32_t* Kb = Kg + (size_t)b * SEQ * DH2 + h * (DK / 2);
    const uint32_t* Vb = Vg + (size_t)b * SEQ * DH2 + h * (DK / 2);

    // Q tile: 128 rows x 32 u32, pure copy (uint4)
#pragma unroll
    for (int i = 0; i < 4; i++) {
        int idx = i * 256 + tid;
        int r = idx >> 3, c = (idx & 7) * 4;
        uint4 v = *(const uint4*)(Qb + (size_t)r * DH2 + c);
        *(uint4*)&Qh[r * KS + c] = v;
    }
    __syncthreads();

    // Hoist Q fragments (warp's 16 rows, 4 k16-chunks); Qh dead after.
    const int r0 = w * 16 + gid;
    uint32_t qf[4][4];
#pragma unroll
    for (int kc = 0; kc < 4; kc++) {
        qf[kc][0] = Qh[r0 * KS + kc * 8 + tig];
        qf[kc][1] = Qh[(r0 + 8) * KS + kc * 8 + tig];
        qf[kc][2] = Qh[r0 * KS + kc * 8 + tig + 4];
        qf[kc][3] = Qh[(r0 + 8) * KS + kc * 8 + tig + 4];
    }

    float o[8][4] = {};
    float m0 = -1e30f, m1 = -1e30f, l0 = 0.f, l1 = 0.f;

    for (int kt = 0; kt < SEQ / 64; kt++) {
        __syncthreads();   // all warps done reading Kh/Vp of previous iter
        const uint32_t* kb = Kb + (size_t)kt * 64 * DH2;
        const uint32_t* vb = Vb + (size_t)kt * 64 * DH2;

        // K tile: 64 x 32 u32, pure copy
#pragma unroll
        for (int i = 0; i < 2; i++) {
            int idx = i * 256 + tid;
            int r = idx >> 3, c = (idx & 7) * 4;
            uint4 v = *(const uint4*)(kb + (size_t)r * DH2 + c);
            *(uint4*)&Kh[r * KS + c] = v;
        }
        // V tile: pair kv rows via prmt -> Vp[kvpair][d] (64 u32 per row)
        {
            int rp = tid >> 3, c0 = (tid & 7) * 4;
            uint4 a4 = *(const uint4*)(vb + (size_t)(2 * rp) * DH2 + c0);
            uint4 b4 = *(const uint4*)(vb + (size_t)(2 * rp + 1) * DH2 + c0);
            uint4 lo = make_uint4(prmt(a4.x, b4.x, 0x5410), prmt(a4.x, b4.x, 0x7632),
                                  prmt(a4.y, b4.y, 0x5410), prmt(a4.y, b4.y, 0x7632));
            uint4 hi = make_uint4(prmt(a4.z, b4.z, 0x5410), prmt(a4.z, b4.z, 0x7632),
                                  prmt(a4.w, b4.w, 0x5410), prmt(a4.w, b4.w, 0x7632));
            *(uint4*)&Vp[rp * VSP + 2 * c0] = lo;
            *(uint4*)&Vp[rp * VSP + 2 * c0 + 4] = hi;
        }
        __syncthreads();

        // S = Q @ K^T  (16 x 64 per warp; 4 k16-chunks x 8 n-tiles)
        float s[8][4] = {};
#pragma unroll
        for (int kc = 0; kc < 4; kc++) {
#pragma unroll
            for (int nt = 0; nt < 8; nt++) {
                uint32_t kf[2];
                int kvp = nt * 8 + gid;
                kf[0] = Kh[kvp * KS + kc * 8 + tig];
                kf[1] = Kh[kvp * KS + kc * 8 + tig + 4];
                mma_f16(s[nt], qf[kc], kf, s[nt]);
            }
        }

        const float scale = 0.125f;   // 1/sqrt(64)
        float mx0 = -1e30f, mx1 = -1e30f;
#pragma unroll
        for (int nt = 0; nt < 8; nt++) {
#pragma unroll
            for (int i = 0; i < 4; i++) s[nt][i] *= scale;
            mx0 = fmaxf(mx0, fmaxf(s[nt][0], s[nt][1]));
            mx1 = fmaxf(mx1, fmaxf(s[nt][2], s[nt][3]));
        }
        mx0 = fmaxf(mx0, __shfl_xor_sync(0xffffffffu, mx0, 1));
        mx0 = fmaxf(mx0, __shfl_xor_sync(0xffffffffu, mx0, 2));
        mx1 = fmaxf(mx1, __shfl_xor_sync(0xffffffffu, mx1, 1));
        mx1 = fmaxf(mx1, __shfl_xor_sync(0xffffffffu, mx1, 2));

        float nm0 = fmaxf(m0, mx0), nm1 = fmaxf(m1, mx1);
        float corr0 = __expf(m0 - nm0), corr1 = __expf(m1 - nm1);
        m0 = nm0; m1 = nm1;

        float rs0 = 0.f, rs1 = 0.f;
#pragma unroll
        for (int nt = 0; nt < 8; nt++) {
            s[nt][0] = __expf(s[nt][0] - nm0);
            s[nt][1] = __expf(s[nt][1] - nm0);
            s[nt][2] = __expf(s[nt][2] - nm1);
            s[nt][3] = __expf(s[nt][3] - nm1);
            rs0 += s[nt][0] + s[nt][1];
            rs1 += s[nt][2] + s[nt][3];
        }
        rs0 += __shfl_xor_sync(0xffffffffu, rs0, 1);
        rs0 += __shfl_xor_sync(0xffffffffu, rs0, 2);
        rs1 += __shfl_xor_sync(0xffffffffu, rs1, 1);
        rs1 += __shfl_xor_sync(0xffffffffu, rs1, 2);
        l0 = l0 * corr0 + rs0;
        l1 = l1 * corr1 + rs1;

#pragma unroll
        for (int nt = 0; nt < 8; nt++) {
            o[nt][0] *= corr0; o[nt][1] *= corr0;
            o[nt][2] *= corr1; o[nt][3] *= corr1;
        }

        // O += P @ V: P A-fragments from registers; V B-fragments from Vp.
#pragma unroll
        for (int kc = 0; kc < 4; kc++) {
            uint32_t pa[4];
            pa[0] = f2h2(s[2 * kc][0], s[2 * kc][1]);
            pa[1] = f2h2(s[2 * kc][2], s[2 * kc][3]);
            pa[2] = f2h2(s[2 * kc + 1][0], s[2 * kc + 1][1]);
            pa[3] = f2h2(s[2 * kc + 1][2], s[2 * kc + 1][3]);
#pragma unroll
            for (int nt = 0; nt < 8; nt++) {
                uint32_t vf[2];
                int col = nt * 8 + gid;
                vf[0] = Vp[(kc * 8 + tig) * VSP + col];
                vf[1] = Vp[(kc * 8 + tig + 4) * VSP + col];
                mma_f16(o[nt], pa, vf, o[nt]);
            }
        }
    }

    // Normalize, convert to fp16 pairs, write packed concat layout
    float inv0 = 1.0f / l0, inv1 = 1.0f / l1;
    uint32_t* obase = Og + ((size_t)b * SEQ + qt * 128) * DH2 + h * (DK / 2);
#pragma unroll
    for (int nt = 0; nt < 8; nt++) {
        int uc = nt * 4 + tig;
        obase[(size_t)r0 * DH2 + uc] = f2h2(o[nt][0] * inv0, o[nt][1] * inv0);
        obase[(size_t)(r0 + 8) * DH2 + uc] = f2h2(o[nt][2] * inv1, o[nt][3] * inv1);
    }
}

// ---------------------------------------------------------------------------
extern "C" void kernel_launch(void* const* d_in, const int* in_sizes, int n_in,
                              void* d_out, int out_size) {
    const float* x  = (const float*)d_in[0];
    const float* Wq = (const float*)d_in[1];
    const float* Wk = (const float*)d_in[2];
    const float* Wv = (const float*)d_in[3];
    const float* Wo = (const float*)d_in[4];
    float* out = (float*)d_out;

    uint32_t *Qh, *Kh, *Vh, *Ah, *Wth;
    cudaGetSymbolAddress((void**)&Qh, g_Qh);
    cudaGetSymbolAddress((void**)&Kh, g_Kh);
    cudaGetSymbolAddress((void**)&Vh, g_Vh);
    cudaGetSymbolAddress((void**)&Ah, g_Ah);
    cudaGetSymbolAddress((void**)&Wth, g_Wth);

    // W^T -> fp16
    transpose_h2_kernel<<<dim3(32, 32, 4), dim3(32, 8)>>>(Wq, Wk, Wv, Wo, Wth);

    // QKV projections -> fp16-packed Q/K/V
    gemm_qkv_f16<<<dim3(8, 32, 3), 256>>>(x, Wth, Qh, Kh, Vh);

    // Attention (fp16 in / fp16 out, register-resident P)
    attn_kernel<<<dim3(SEQ / 128, NHEAD, BATCH), 256>>>(Qh, Kh, Vh, Ah);

    // Output projection (fp16 A-side, f32 out)
    gemm_o_f16<<<dim3(8, 32, 1), 256>>>(Ah, Wth, out);
}